// round 14
// baseline (speedup 1.0000x reference)
#include <cuda_runtime.h>
#include <cooperative_groups.h>

namespace cg = cooperative_groups;

typedef unsigned long long u64;

// Problem constants (fixed by the benchmark)
#define BATCH  512
#define TLEN   1024
#define DDIM   64
#define UDIM   128
#define ROWS   8          // batch rows per cluster
#define NTHR   256        // 8 warps; 4 k-chunks, one per 2-warp group (tid>>6)
#define WSTRIDE 196       // 192 k-values + 4 pad words (conflict-free, 16B-aligned)

// Shared memory layout (floats)
//   Wsm  : 256 cols * 196 = 50176   @0        (k-PERMUTED: [x(64)|local-h(64)|peer-h(64)])
//   zbuf : 2 * 8 * 192 = 3072       @50176    (per row: [x(64)|own-h(64)|peer-h(64)], dbl-buf)
//   gsm  : 2 * 2048 = 4096          @53248    (TWO fp32 partial banks, 2-phase reduction)
//   bias : 256 (ALIASES gsm; consumed into regs before first gsm write)
// total 57344 floats = 229376 bytes (<= 231424 proven cap)
#define OFF_Z 50176
#define OFF_G 53248
#define OFF_BIAS OFF_G
#define ZROW  192
#define ZPAR  1536
#define SMEM_FLOATS 57344
#define SMEM_BYTES  (SMEM_FLOATS * 4)

// Split cluster barrier (warp-uniform call sites -> .aligned legal)
#define CLUSTER_ARRIVE() asm volatile("barrier.cluster.arrive.aligned;" ::: "memory")
#define CLUSTER_WAIT()   asm volatile("barrier.cluster.wait.aligned;"   ::: "memory")

__device__ __forceinline__ float sigf(float x) {
    return __fdividef(1.0f, 1.0f + __expf(-x));
}
__device__ __forceinline__ float tanhf_fast(float x) {
    return 1.0f - __fdividef(2.0f, 1.0f + __expf(2.0f * x));
}

// ---- packed f32x2 helpers (PTX-only; ptxas never auto-fuses FFMA2) ----
__device__ __forceinline__ void fma2(u64& acc, u64 a, u64 b) {
    asm("fma.rn.f32x2 %0, %1, %2, %0;" : "+l"(acc) : "l"(a), "l"(b));
}
__device__ __forceinline__ u64 pack2(float lo, float hi) {
    u64 r;
    asm("mov.b64 %0, {%1, %2};" : "=l"(r) : "f"(lo), "f"(hi));
    return r;
}
__device__ __forceinline__ float fold2(u64 v) {
    float lo, hi;
    asm("mov.b64 {%0, %1}, %2;" : "=f"(lo), "=f"(hi) : "l"(v));
    return lo + hi;
}

// NS slices of the k-dimension starting at s0 (u64x2 granularity, 4 floats each).
// 4 gate-columns of one u-output; 8 batch rows. All broadcasts are warp-uniform.
template <int NS>
__device__ __forceinline__ void fma_slices(
    u64 (&acc)[4][8],
    const ulonglong2* __restrict__ W0, const ulonglong2* __restrict__ W1,
    const ulonglong2* __restrict__ W2, const ulonglong2* __restrict__ W3,
    const ulonglong2* __restrict__ zp, int s0)
{
    #pragma unroll 4
    for (int i = 0; i < NS; i++) {
        int s = s0 + i;
        ulonglong2 w0 = W0[s], w1 = W1[s], w2 = W2[s], w3 = W3[s];
        #pragma unroll
        for (int r = 0; r < 8; r++) {
            ulonglong2 v = zp[r * 48 + s];     // warp-uniform broadcast
            fma2(acc[0][r], v.x, w0.x); fma2(acc[0][r], v.y, w0.y);
            fma2(acc[1][r], v.x, w1.x); fma2(acc[1][r], v.y, w1.y);
            fma2(acc[2][r], v.x, w2.x); fma2(acc[2][r], v.y, w2.y);
            fma2(acc[3][r], v.x, w3.x); fma2(acc[3][r], v.y, w3.y);
        }
    }
}

extern __shared__ float smem[];

__global__ void __launch_bounds__(NTHR, 1) __cluster_dims__(2, 1, 1)
lstm_persistent_kernel(
    const float* __restrict__ x,
    const float* __restrict__ Wf, const float* __restrict__ Uf, const float* __restrict__ bf,
    const float* __restrict__ Wi, const float* __restrict__ Ui, const float* __restrict__ bi,
    const float* __restrict__ Wc, const float* __restrict__ Uc, const float* __restrict__ bc,
    const float* __restrict__ Wo, const float* __restrict__ Uo, const float* __restrict__ bo,
    float* __restrict__ out)
{
    float* Wsm  = smem;
    float* zbuf = smem + OFF_Z;
    float* gsm  = smem + OFF_G;
    float* bsm  = smem + OFF_BIAS;   // aliases gsm; valid only until first gsm write

    cg::cluster_group cluster = cg::this_cluster();
    const int q   = (int)cluster.block_rank();     // 0/1: which 64-output half of U this CTA owns
    const int tid = threadIdx.x;
    const int b0  = (blockIdx.x >> 1) * ROWS;

    float* zbuf_peer = cluster.map_shared_rank(zbuf, q ^ 1);

    // ---- one-time: k-PERMUTED weights into smem, column-major [col][kperm] ----
    //   kperm 0..63    -> x weight, d = kp
    //   kperm 64..127  -> U row j = q*64 + (kp-64)      (locally-produced h)
    //   kperm 128..191 -> U row j = (q^1)*64 + (kp-128) (peer-pushed h)
    const float* Wg[4] = {Wf, Wi, Wc, Wo};
    const float* Ug[4] = {Uf, Ui, Uc, Uo};
    const float* bg[4] = {bf, bi, bc, bo};

    for (int idx = tid; idx < 256 * 192; idx += NTHR) {
        int col = idx / 192;
        int kp  = idx - col * 192;
        int g = col >> 6, uu = col & 63;
        float w;
        if (kp < 64)        w = Wg[g][kp * UDIM + q * 64 + uu];
        else if (kp < 128)  w = Ug[g][(q * 64 + kp - 64) * UDIM + q * 64 + uu];
        else                w = Ug[g][((q ^ 1) * 64 + kp - 128) * UDIM + q * 64 + uu];
        Wsm[col * WSTRIDE + kp] = w;
    }
    if (tid < 64) {
        #pragma unroll
        for (int g = 0; g < 4; g++) bsm[g * 64 + tid] = bg[g][q * 64 + tid];
    }

    // zero zbuf (both parities: h regions must start at 0), load x_{t=0}
    for (int idx = tid; idx < 2 * ZPAR; idx += NTHR) zbuf[idx] = 0.0f;
    __syncthreads();
    {
        int r0 = tid >> 6, d0 = tid & 63;
        zbuf[r0 * ZROW + d0]       = x[(b0 + r0)     * (TLEN * DDIM) + d0];
        zbuf[(r0 + 4) * ZROW + d0] = x[(b0 + r0 + 4) * (TLEN * DDIM) + d0];
    }

    // ---- ownership: chunk = tid>>6 (2-warp group) owns k-window [48*chunk, 48*chunk+48)
    //      thread covers the 4 gate-columns of u-output uu = tid&63, all 8 rows ----
    const int chunk = tid >> 6;
    const int ct2   = tid & 63;
    const ulonglong2* W0 = (const ulonglong2*)(Wsm + (ct2      ) * WSTRIDE);
    const ulonglong2* W1 = (const ulonglong2*)(Wsm + (ct2 +  64) * WSTRIDE);
    const ulonglong2* W2 = (const ulonglong2*)(Wsm + (ct2 + 128) * WSTRIDE);
    const ulonglong2* W3 = (const ulonglong2*)(Wsm + (ct2 + 192) * WSTRIDE);

    __syncthreads();   // x load + weights + bias visible

    // bias only into chunk 0's partials (bsm aliases gsm -> consume, then barrier)
    u64 bp[4];
    #pragma unroll
    for (int g = 0; g < 4; g++)
        bp[g] = (chunk == 0) ? pack2(bsm[g * 64 + ct2], 0.0f) : 0ull;
    __syncthreads();   // bias reads done before first gsm write

    // combine-phase state cells (fixed per thread): cells tid and tid+256
    float cs0 = 0.0f, cs1 = 0.0f, h0 = 0.0f, h1 = 0.0f;
    const int rr = tid >> 6;          // combine rows rr and rr+4
    const int cu = tid & 63;          // combine u-index (local)
    const int pr = tid >> 6, pd = tid & 63;   // x-prefetch mapping

    CLUSTER_ARRIVE();  // seed arrive/wait pipeline (matches step-0 wait)

    for (int t = 0; t < TLEN; t++) {
        const int p = t & 1;

        // ---- prefetch x_{t+1} (overlaps the whole FMA phase) ----
        float pf0 = 0.0f, pf1 = 0.0f;
        if (t + 1 < TLEN) {
            pf0 = x[(b0 + pr)     * (TLEN * DDIM) + (t + 1) * DDIM + pd];
            pf1 = x[(b0 + pr + 4) * (TLEN * DDIM) + (t + 1) * DDIM + pd];
        }

        u64 acc[4][8];
        #pragma unroll
        for (int r = 0; r < 8; r++) {
            acc[0][r] = bp[0]; acc[1][r] = bp[1]; acc[2][r] = bp[2]; acc[3][r] = bp[3];
        }

        const ulonglong2* zp = (const ulonglong2*)(zbuf + p * ZPAR);  // [8 rows][48 u64x2]

        // k-permuted space: slices 0..31 = x + local-h (pre-wait), 32..47 = peer-h
        if (chunk < 2) {
            fma_slices<12>(acc, W0, W1, W2, W3, zp, chunk * 12);
            CLUSTER_WAIT();            // executed once per step by every warp
        } else if (chunk == 2) {
            fma_slices<8>(acc, W0, W1, W2, W3, zp, 24);
            CLUSTER_WAIT();            // acquire: peer's h pushes of step t-1 visible
            fma_slices<4>(acc, W0, W1, W2, W3, zp, 32);
        } else {
            CLUSTER_WAIT();
            fma_slices<12>(acc, W0, W1, W2, W3, zp, 36);
        }

        // ---- 2-phase partial reduction into TWO fp32 banks ----
        float* bank = gsm + (chunk & 1) * 2048;   // chunks 0,2 -> A; 1,3 -> B
        if (chunk < 2) {
            #pragma unroll
            for (int g = 0; g < 4; g++)
                #pragma unroll
                for (int r = 0; r < 8; r++)
                    bank[g * 512 + r * 64 + ct2] = fold2(acc[g][r]);
        }
        __syncthreads();                           // B1a: phase-1 stores done

        // stash x prefetch (other parity; readers gated by B1b+B2)
        if (t + 1 < TLEN) {
            zbuf[(p ^ 1) * ZPAR + pr * ZROW + pd]       = pf0;
            zbuf[(p ^ 1) * ZPAR + (pr + 4) * ZROW + pd] = pf1;
        }

        if (chunk >= 2) {                          // phase 2: read-add-write (no race: own bank)
            #pragma unroll
            for (int g = 0; g < 4; g++)
                #pragma unroll
                for (int r = 0; r < 8; r++) {
                    int ix = g * 512 + r * 64 + ct2;
                    bank[ix] += fold2(acc[g][r]);
                }
        }
        __syncthreads();                           // B1b: banks complete

        // ---- combine (2 cells per thread, c-state in registers) ----
        float* zl = zbuf      + (p ^ 1) * ZPAR + 64  + cu;   // own-h region
        float* zq = zbuf_peer + (p ^ 1) * ZPAR + 128 + cu;   // peer's peer-h region
        {
            int i = tid;                                      // cell (rr, cu)
            float gf = gsm[i]        + gsm[2048 + i];
            float gi = gsm[512 + i]  + gsm[2560 + i];
            float gc = gsm[1024 + i] + gsm[3072 + i];
            float go = gsm[1536 + i] + gsm[3584 + i];
            float cn = fmaf(sigf(gf), cs0, sigf(gi) * tanhf_fast(gc));
            cs0 = cn;
            h0 = sigf(go) * tanhf_fast(cn);
            zl[rr * ZROW] = h0;
            zq[rr * ZROW] = h0;                               // DSMEM push to peer
        }
        {
            int i = tid + 256;                                // cell (rr+4, cu)
            float gf = gsm[i]        + gsm[2048 + i];
            float gi = gsm[512 + i]  + gsm[2560 + i];
            float gc = gsm[1024 + i] + gsm[3072 + i];
            float go = gsm[1536 + i] + gsm[3584 + i];
            float cn = fmaf(sigf(gf), cs1, sigf(gi) * tanhf_fast(gc));
            cs1 = cn;
            h1 = sigf(go) * tanhf_fast(cn);
            zl[(rr + 4) * ZROW] = h1;
            zq[(rr + 4) * ZROW] = h1;
        }
        __syncthreads();                           // B2: local h/x writes ordered

        CLUSTER_ARRIVE();  // release: peer pushes published; wait deferred into t+1
    }

    // final h is in registers (cells tid, tid+256)
    out[(b0 + rr)     * UDIM + q * 64 + cu] = h0;
    out[(b0 + rr + 4) * UDIM + q * 64 + cu] = h1;

    CLUSTER_WAIT();    // drain final arrives; peer done touching our smem before exit
}

extern "C" void kernel_launch(void* const* d_in, const int* in_sizes, int n_in,
                              void* d_out, int out_size)
{
    const float* x  = (const float*)d_in[0];
    const float* Wf = (const float*)d_in[1];
    const float* Uf = (const float*)d_in[2];
    const float* bf = (const float*)d_in[3];
    const float* Wi = (const float*)d_in[4];
    const float* Ui = (const float*)d_in[5];
    const float* bi = (const float*)d_in[6];
    const float* Wc = (const float*)d_in[7];
    const float* Uc = (const float*)d_in[8];
    const float* bc = (const float*)d_in[9];
    const float* Wo = (const float*)d_in[10];
    const float* Uo = (const float*)d_in[11];
    const float* bo = (const float*)d_in[12];
    float* out = (float*)d_out;

    cudaFuncSetAttribute(lstm_persistent_kernel,
                         cudaFuncAttributeMaxDynamicSharedMemorySize, SMEM_BYTES);

    // 64 clusters x 2 CTAs = 128 CTAs; each cluster owns 8 batch rows.
    lstm_persistent_kernel<<<128, NTHR, SMEM_BYTES>>>(
        x, Wf, Uf, bf, Wi, Ui, bi, Wc, Uc, bc, Wo, Uo, bo, out);
}

// round 15
// speedup vs baseline: 1.0692x; 1.0692x over previous
#include <cuda_runtime.h>
#include <cooperative_groups.h>

namespace cg = cooperative_groups;

typedef unsigned long long u64;

// Problem constants (fixed by the benchmark)
#define BATCH  512
#define TLEN   1024
#define DDIM   64
#define UDIM   128
#define ROWS   8          // batch rows per cluster
#define NTHR   256        // 8 warps; 4 k-chunks, one per 2-warp group (tid>>6)
#define WSTRIDE 196       // 192 k-values + 4 pad words (conflict-free, 16B-aligned)

// Shared memory layout (floats)
//   Wsm  : 256 cols * 196 = 50176   @0
//     k-INTERLEAVED per column: chunk c window [48c,48c+48) =
//     [ x(16c..16c+15) | U_local rows q*64+16c.. | U_peer rows (q^1)*64+16c.. ]
//   zbuf : 2 * 8 * 192 = 3072       @50176   (rows use the SAME interleaved layout)
//   gsm  : 2 * 2048 = 4096          @53248   (TWO fp32 partial banks, 2-phase reduction)
//   bias : 256 (ALIASES gsm; consumed into regs before first gsm write)
// total 57344 floats = 229376 bytes
#define OFF_Z 50176
#define OFF_G 53248
#define OFF_BIAS OFF_G
#define ZROW  192
#define ZPAR  1536
#define SMEM_FLOATS 57344
#define SMEM_BYTES  (SMEM_FLOATS * 4)

// Split cluster barrier — SINGLE uniform call site per step for every warp.
#define CLUSTER_ARRIVE() asm volatile("barrier.cluster.arrive.aligned;" ::: "memory")
#define CLUSTER_WAIT()   asm volatile("barrier.cluster.wait.aligned;"   ::: "memory")

__device__ __forceinline__ float sigf(float x) {
    return __fdividef(1.0f, 1.0f + __expf(-x));
}
__device__ __forceinline__ float tanhf_fast(float x) {
    return 1.0f - __fdividef(2.0f, 1.0f + __expf(2.0f * x));
}

// ---- packed f32x2 helpers (PTX-only; ptxas never auto-fuses FFMA2) ----
__device__ __forceinline__ void fma2(u64& acc, u64 a, u64 b) {
    asm("fma.rn.f32x2 %0, %1, %2, %0;" : "+l"(acc) : "l"(a), "l"(b));
}
__device__ __forceinline__ u64 pack2(float lo, float hi) {
    u64 r;
    asm("mov.b64 %0, {%1, %2};" : "=l"(r) : "f"(lo), "f"(hi));
    return r;
}
__device__ __forceinline__ float fold2(u64 v) {
    float lo, hi;
    asm("mov.b64 {%0, %1}, %2;" : "=f"(lo), "=f"(hi) : "l"(v));
    return lo + hi;
}

// NS k-slices starting at s0 (ulonglong2 = 4 floats each); 4 gate-cols, 8 rows.
template <int NS>
__device__ __forceinline__ void fma_slices(
    u64 (&acc)[4][8],
    const ulonglong2* __restrict__ W0, const ulonglong2* __restrict__ W1,
    const ulonglong2* __restrict__ W2, const ulonglong2* __restrict__ W3,
    const ulonglong2* __restrict__ zp, int s0)
{
    #pragma unroll 4
    for (int i = 0; i < NS; i++) {
        int s = s0 + i;
        ulonglong2 w0 = W0[s], w1 = W1[s], w2 = W2[s], w3 = W3[s];
        #pragma unroll
        for (int r = 0; r < 8; r++) {
            ulonglong2 v = zp[r * 48 + s];     // warp-uniform broadcast
            fma2(acc[0][r], v.x, w0.x); fma2(acc[0][r], v.y, w0.y);
            fma2(acc[1][r], v.x, w1.x); fma2(acc[1][r], v.y, w1.y);
            fma2(acc[2][r], v.x, w2.x); fma2(acc[2][r], v.y, w2.y);
            fma2(acc[3][r], v.x, w3.x); fma2(acc[3][r], v.y, w3.y);
        }
    }
}

extern __shared__ float smem[];

__global__ void __launch_bounds__(NTHR, 1) __cluster_dims__(2, 1, 1)
lstm_persistent_kernel(
    const float* __restrict__ x,
    const float* __restrict__ Wf, const float* __restrict__ Uf, const float* __restrict__ bf,
    const float* __restrict__ Wi, const float* __restrict__ Ui, const float* __restrict__ bi,
    const float* __restrict__ Wc, const float* __restrict__ Uc, const float* __restrict__ bc,
    const float* __restrict__ Wo, const float* __restrict__ Uo, const float* __restrict__ bo,
    float* __restrict__ out)
{
    float* Wsm  = smem;
    float* zbuf = smem + OFF_Z;
    float* gsm  = smem + OFF_G;
    float* bsm  = smem + OFF_BIAS;   // aliases gsm; valid only until first gsm write

    cg::cluster_group cluster = cg::this_cluster();
    const int q   = (int)cluster.block_rank();
    const int tid = threadIdx.x;
    const int b0  = (blockIdx.x >> 1) * ROWS;

    float* zbuf_peer = cluster.map_shared_rank(zbuf, q ^ 1);

    // ---- one-time: k-INTERLEAVED weights, column-major [col][kperm] ----
    // kperm = 48c + off:  off<16  -> x weight d = 16c+off
    //                     off<32  -> U row q*64   + 16c + (off-16)   (local h)
    //                     else    -> U row (q^1)*64 + 16c + (off-32) (peer h)
    const float* Wg[4] = {Wf, Wi, Wc, Wo};
    const float* Ug[4] = {Uf, Ui, Uc, Uo};
    const float* bg[4] = {bf, bi, bc, bo};

    for (int idx = tid; idx < 256 * 192; idx += NTHR) {
        int col = idx / 192;
        int kp  = idx - col * 192;
        int c   = kp >> 4 >> 2;        // kp / 48 would be wrong; compute properly below
        c = kp / 48;
        int off = kp - c * 48;
        int g = col >> 6, uu = col & 63;
        float w;
        if (off < 16)       w = Wg[g][(c * 16 + off) * UDIM + q * 64 + uu];
        else if (off < 32)  w = Ug[g][(q * 64 + c * 16 + off - 16) * UDIM + q * 64 + uu];
        else                w = Ug[g][((q ^ 1) * 64 + c * 16 + off - 32) * UDIM + q * 64 + uu];
        Wsm[col * WSTRIDE + kp] = w;
    }
    if (tid < 64) {
        #pragma unroll
        for (int g = 0; g < 4; g++) bsm[g * 64 + tid] = bg[g][q * 64 + tid];
    }

    // zero zbuf (h slots must start at 0), then x_{t=0} into interleaved x slots
    for (int idx = tid; idx < 2 * ZPAR; idx += NTHR) zbuf[idx] = 0.0f;
    __syncthreads();
    {
        int r0 = tid >> 6, d0 = tid & 63;
        int xp = (d0 >> 4) * 48 + (d0 & 15);
        zbuf[r0 * ZROW + xp]       = x[(b0 + r0)     * (TLEN * DDIM) + d0];
        zbuf[(r0 + 4) * ZROW + xp] = x[(b0 + r0 + 4) * (TLEN * DDIM) + d0];
    }

    // ---- ownership: chunk = tid>>6 owns k-window [48*chunk, 48*chunk+48)
    //      (16 x + 16 local-h + 16 peer-h); u-output uu = tid&63, all 8 rows ----
    const int chunk = tid >> 6;
    const int ct2   = tid & 63;
    const ulonglong2* W0 = (const ulonglong2*)(Wsm + (ct2      ) * WSTRIDE);
    const ulonglong2* W1 = (const ulonglong2*)(Wsm + (ct2 +  64) * WSTRIDE);
    const ulonglong2* W2 = (const ulonglong2*)(Wsm + (ct2 + 128) * WSTRIDE);
    const ulonglong2* W3 = (const ulonglong2*)(Wsm + (ct2 + 192) * WSTRIDE);
    const int s_pre  = chunk * 12;       // 8 slices: x + local-h
    const int s_post = chunk * 12 + 8;   // 4 slices: peer-h

    __syncthreads();   // weights + x visible

    // bias only into chunk 0's partials (bsm aliases gsm -> consume, then barrier)
    u64 bp[4];
    #pragma unroll
    for (int g = 0; g < 4; g++)
        bp[g] = (chunk == 0) ? pack2(bsm[g * 64 + ct2], 0.0f) : 0ull;
    __syncthreads();   // bias reads done before first gsm write

    // combine-phase state (cells tid and tid+256), c-state in registers
    float cs0 = 0.0f, cs1 = 0.0f, h0 = 0.0f, h1 = 0.0f;
    const int rr = tid >> 6;
    const int cu = tid & 63;
    const int hpos_own  = (cu >> 4) * 48 + 16 + (cu & 15);
    const int hpos_peer = (cu >> 4) * 48 + 32 + (cu & 15);
    const int pr = tid >> 6, pd = tid & 63;
    const int xpos = (pd >> 4) * 48 + (pd & 15);

    CLUSTER_ARRIVE();  // seed arrive/wait pipeline (matches step-0 wait)

    for (int t = 0; t < TLEN; t++) {
        const int p = t & 1;

        // ---- prefetch x_{t+1} (overlaps the whole FMA phase) ----
        float pf0 = 0.0f, pf1 = 0.0f;
        if (t + 1 < TLEN) {
            pf0 = x[(b0 + pr)     * (TLEN * DDIM) + (t + 1) * DDIM + pd];
            pf1 = x[(b0 + pr + 4) * (TLEN * DDIM) + (t + 1) * DDIM + pd];
        }

        u64 acc[4][8];
        #pragma unroll
        for (int r = 0; r < 8; r++) {
            acc[0][r] = bp[0]; acc[1][r] = bp[1]; acc[2][r] = bp[2]; acc[3][r] = bp[3];
        }

        const ulonglong2* zp = (const ulonglong2*)(zbuf + p * ZPAR);  // [8 rows][48 u64x2]

        // ---- UNIFORM path: 8 pre-wait slices, wait, 4 post-wait slices ----
        fma_slices<8>(acc, W0, W1, W2, W3, zp, s_pre);
        CLUSTER_WAIT();               // acquire: peer's h pushes of step t-1 visible
        fma_slices<4>(acc, W0, W1, W2, W3, zp, s_post);

        // ---- 2-phase partial reduction into TWO fp32 banks ----
        float* bank = gsm + (chunk & 1) * 2048;   // chunks 0,2 -> A; 1,3 -> B
        if (chunk < 2) {                          // phase 1: direct store
            #pragma unroll
            for (int g = 0; g < 4; g++)
                #pragma unroll
                for (int r = 0; r < 8; r++)
                    bank[g * 512 + r * 64 + ct2] = fold2(acc[g][r]);
        }
        __syncthreads();                          // B1a: phase-1 stores done

        // stash x prefetch (other parity; readers gated by B2)
        if (t + 1 < TLEN) {
            zbuf[(p ^ 1) * ZPAR + pr * ZROW + xpos]       = pf0;
            zbuf[(p ^ 1) * ZPAR + (pr + 4) * ZROW + xpos] = pf1;
        }

        if (chunk >= 2) {                         // phase 2: read-add-write (own bank)
            #pragma unroll
            for (int g = 0; g < 4; g++)
                #pragma unroll
                for (int r = 0; r < 8; r++) {
                    int ix = g * 512 + r * 64 + ct2;
                    bank[ix] += fold2(acc[g][r]);
                }
        }
        __syncthreads();                          // B1b: banks complete

        // ---- combine (2 cells/thread); push h into own local-h slot + peer's peer-h slot ----
        float* zl = zbuf      + (p ^ 1) * ZPAR;
        float* zq = zbuf_peer + (p ^ 1) * ZPAR;
        {
            int i = tid;                          // cell (rr, cu)
            float gf = gsm[i]        + gsm[2048 + i];
            float gi = gsm[512 + i]  + gsm[2560 + i];
            float gc = gsm[1024 + i] + gsm[3072 + i];
            float go = gsm[1536 + i] + gsm[3584 + i];
            float cn = fmaf(sigf(gf), cs0, sigf(gi) * tanhf_fast(gc));
            cs0 = cn;
            h0 = sigf(go) * tanhf_fast(cn);
            zl[rr * ZROW + hpos_own]  = h0;
            zq[rr * ZROW + hpos_peer] = h0;       // DSMEM push to peer
        }
        {
            int i = tid + 256;                    // cell (rr+4, cu)
            float gf = gsm[i]        + gsm[2048 + i];
            float gi = gsm[512 + i]  + gsm[2560 + i];
            float gc = gsm[1024 + i] + gsm[3072 + i];
            float go = gsm[1536 + i] + gsm[3584 + i];
            float cn = fmaf(sigf(gf), cs1, sigf(gi) * tanhf_fast(gc));
            cs1 = cn;
            h1 = sigf(go) * tanhf_fast(cn);
            zl[(rr + 4) * ZROW + hpos_own]  = h1;
            zq[(rr + 4) * ZROW + hpos_peer] = h1;
        }
        __syncthreads();                          // B2: local h/x writes ordered

        CLUSTER_ARRIVE();  // release: peer pushes published; wait deferred into t+1
    }

    // final h is in registers (cells tid, tid+256)
    out[(b0 + rr)     * UDIM + q * 64 + cu] = h0;
    out[(b0 + rr + 4) * UDIM + q * 64 + cu] = h1;

    CLUSTER_WAIT();    // drain final arrives; peer done touching our smem before exit
}

extern "C" void kernel_launch(void* const* d_in, const int* in_sizes, int n_in,
                              void* d_out, int out_size)
{
    const float* x  = (const float*)d_in[0];
    const float* Wf = (const float*)d_in[1];
    const float* Uf = (const float*)d_in[2];
    const float* bf = (const float*)d_in[3];
    const float* Wi = (const float*)d_in[4];
    const float* Ui = (const float*)d_in[5];
    const float* bi = (const float*)d_in[6];
    const float* Wc = (const float*)d_in[7];
    const float* Uc = (const float*)d_in[8];
    const float* bc = (const float*)d_in[9];
    const float* Wo = (const float*)d_in[10];
    const float* Uo = (const float*)d_in[11];
    const float* bo = (const float*)d_in[12];
    float* out = (float*)d_out;

    cudaFuncSetAttribute(lstm_persistent_kernel,
                         cudaFuncAttributeMaxDynamicSharedMemorySize, SMEM_BYTES);

    // 64 clusters x 2 CTAs = 128 CTAs; each cluster owns 8 batch rows.
    lstm_persistent_kernel<<<128, NTHR, SMEM_BYTES>>>(
        x, Wf, Uf, bf, Wi, Ui, bi, Wc, Uc, bc, Wo, Uo, bo, out);
}